// round 4
// baseline (speedup 1.0000x reference)
#include <cuda_runtime.h>

// crossCorrelation3D: local 9x9 windowed cross-correlation loss.
// input (32,1,512,512) fp32, target (32,1,512,512) fp32 -> scalar.
//
// Separable 9x9 box sums: per-row horizontal sliding sums (hsum9) +
// vertical running sums with a thread-private 9-row hsum ring in shared.
// Row data loaded DIRECTLY from global (3 overlapping LDG.128 per array,
// halo via neighbor float4, L1-resident) -> no staging, NO barriers in the
// main loop. Grid = 9 ytiles x 32 batches = 288 CTAs (occ 2, 97% balance).

#define IMG_W 512
#define IMG_H 512
#define NB    32
#define YT    9
#define HT    57            // nominal rows/tile (last tile = 56)
#define NT    128           // threads/block, 4 cols each -> 512 cols
#define RING_F (9*5*512)    // 92160 floats? no: elements = 23040 -> 92KB bytes
#define NPART (YT*NB)       // 288

__device__ float g_part[NPART];

__device__ __forceinline__ void hsum9(const float* v, float* h) {
    float s = ((v[0] + v[1]) + (v[2] + v[3])) +
              ((v[4] + v[5]) + (v[6] + v[7])) + v[8];
    h[0] = s;
    s = s - v[0] + v[9];  h[1] = s;
    s = s - v[1] + v[10]; h[2] = s;
    s = s - v[2] + v[11]; h[3] = s;
}

__device__ __forceinline__ float ccval(float sI, float sT, float sII, float sTT, float sIT) {
    const float inv = 1.0f / 81.0f;
    float cross = fmaf(-(sI * sT), inv, sIT);
    float tvar  = fmaf(-(sT * sT), inv, sTT);
    float ivar  = fmaf(-(sI * sI), inv, sII);
    float den   = fmaf(tvar, ivar, 1e-5f);
    return __fdividef(cross * cross, den);
}

__device__ __forceinline__ float4 norm4(float4 t) {
    return make_float4(fmaf(t.x, 0.5f, 0.5f), fmaf(t.y, 0.5f, 0.5f),
                       fmaf(t.z, 0.5f, 0.5f), fmaf(t.w, 0.5f, 0.5f));
}

// Load one row (3 overlapping float4: cols 4t-4..4t+7). Zeros when row OOR
// or at column edges. For T, normalization applied only to valid data.
__device__ __forceinline__ void loadrowI(const float* __restrict__ R, int yi, int tid,
                                         float4& a0, float4& a1, float4& a2) {
    float4 z = make_float4(0.f, 0.f, 0.f, 0.f);
    if (yi >= 0 && yi < IMG_H) {
        const float4* p = (const float4*)(R + (size_t)yi * IMG_W);
        a1 = __ldg(&p[tid]);
        a0 = (tid > 0)      ? __ldg(&p[tid - 1]) : z;
        a2 = (tid < NT - 1) ? __ldg(&p[tid + 1]) : z;
    } else { a0 = z; a1 = z; a2 = z; }
}

__device__ __forceinline__ void loadrowT(const float* __restrict__ R, int yi, int tid,
                                         float4& a0, float4& a1, float4& a2) {
    float4 z = make_float4(0.f, 0.f, 0.f, 0.f);
    if (yi >= 0 && yi < IMG_H) {
        const float4* p = (const float4*)(R + (size_t)yi * IMG_W);
        a1 = norm4(__ldg(&p[tid]));
        a0 = (tid > 0)      ? norm4(__ldg(&p[tid - 1])) : z;
        a2 = (tid < NT - 1) ? norm4(__ldg(&p[tid + 1])) : z;
    } else { a0 = z; a1 = z; a2 = z; }
}

__global__ __launch_bounds__(NT)
void cc_kernel(const float* __restrict__ inp, const float* __restrict__ tgt) {
    extern __shared__ float ring[];   // 9 rows x 5 channels x 512 cols (thread-private cols)

    const int tid = threadIdx.x;
    const int bx  = blockIdx.x;       // ytile 0..8
    const int b   = blockIdx.y;       // batch
    const int y0  = bx * HT;
    const int rows_out = min(HT, IMG_H - y0);
    const int iters = rows_out + 8;

    const float* Ib = inp + (size_t)b * IMG_H * IMG_W;
    const float* Tb = tgt + (size_t)b * IMG_H * IMG_W;

    // zero ring (thread-private columns -> no sync needed)
    {
        float4 z = make_float4(0.f, 0.f, 0.f, 0.f);
        #pragma unroll
        for (int r = 0; r < 45; r++)
            *(float4*)&ring[r * 512 + 4 * tid] = z;
    }

    float4 vI  = make_float4(0.f, 0.f, 0.f, 0.f);
    float4 vT = vI, vII = vI, vTT = vI, vIT = vI;
    float acc = 0.f;
    int rpos = 0;

    // software pipeline: prefetch row y0-4
    float4 cI0, cI1, cI2, cT0, cT1, cT2;
    loadrowI(Ib, y0 - 4, tid, cI0, cI1, cI2);
    loadrowT(Tb, y0 - 4, tid, cT0, cT1, cT2);

    for (int it = 0; it < iters; ++it) {
        // prefetch next row while processing current
        float4 nI0, nI1, nI2, nT0, nT1, nT2;
        loadrowI(Ib, y0 - 3 + it, tid, nI0, nI1, nI2);
        loadrowT(Tb, y0 - 3 + it, tid, nT0, nT1, nT2);

        float iv[12], tv[12];
        iv[0]=cI0.x; iv[1]=cI0.y; iv[2]=cI0.z; iv[3]=cI0.w;
        iv[4]=cI1.x; iv[5]=cI1.y; iv[6]=cI1.z; iv[7]=cI1.w;
        iv[8]=cI2.x; iv[9]=cI2.y; iv[10]=cI2.z; iv[11]=cI2.w;
        tv[0]=cT0.x; tv[1]=cT0.y; tv[2]=cT0.z; tv[3]=cT0.w;
        tv[4]=cT1.x; tv[5]=cT1.y; tv[6]=cT1.z; tv[7]=cT1.w;
        tv[8]=cT2.x; tv[9]=cT2.y; tv[10]=cT2.z; tv[11]=cT2.w;

        float pII[12], pTT[12], pIT[12];
        #pragma unroll
        for (int j = 0; j < 12; j++) {
            pII[j] = iv[j] * iv[j];
            pTT[j] = tv[j] * tv[j];
            pIT[j] = iv[j] * tv[j];
        }

        float hI[4], hT[4], hII[4], hTT[4], hIT[4];
        hsum9(iv,  hI);
        hsum9(tv,  hT);
        hsum9(pII, hII);
        hsum9(pTT, hTT);
        hsum9(pIT, hIT);

        // ring update + vertical running sums (thread-private, no sync)
        float* rb = ring + rpos * (5 * 512) + 4 * tid;
        float4 o;
        o = *(float4*)&rb[0];
        vI.x += hI[0] - o.x;  vI.y += hI[1] - o.y;  vI.z += hI[2] - o.z;  vI.w += hI[3] - o.w;
        *(float4*)&rb[0] = make_float4(hI[0], hI[1], hI[2], hI[3]);
        o = *(float4*)&rb[512];
        vT.x += hT[0] - o.x;  vT.y += hT[1] - o.y;  vT.z += hT[2] - o.z;  vT.w += hT[3] - o.w;
        *(float4*)&rb[512] = make_float4(hT[0], hT[1], hT[2], hT[3]);
        o = *(float4*)&rb[1024];
        vII.x += hII[0] - o.x; vII.y += hII[1] - o.y; vII.z += hII[2] - o.z; vII.w += hII[3] - o.w;
        *(float4*)&rb[1024] = make_float4(hII[0], hII[1], hII[2], hII[3]);
        o = *(float4*)&rb[1536];
        vTT.x += hTT[0] - o.x; vTT.y += hTT[1] - o.y; vTT.z += hTT[2] - o.z; vTT.w += hTT[3] - o.w;
        *(float4*)&rb[1536] = make_float4(hTT[0], hTT[1], hTT[2], hTT[3]);
        o = *(float4*)&rb[2048];
        vIT.x += hIT[0] - o.x; vIT.y += hIT[1] - o.y; vIT.z += hIT[2] - o.z; vIT.w += hIT[3] - o.w;
        *(float4*)&rb[2048] = make_float4(hIT[0], hIT[1], hIT[2], hIT[3]);
        rpos = (rpos == 8) ? 0 : rpos + 1;

        if (it >= 8) {
            acc += ccval(vI.x, vT.x, vII.x, vTT.x, vIT.x);
            acc += ccval(vI.y, vT.y, vII.y, vTT.y, vIT.y);
            acc += ccval(vI.z, vT.z, vII.z, vTT.z, vIT.z);
            acc += ccval(vI.w, vT.w, vII.w, vTT.w, vIT.w);
        }

        cI0 = nI0; cI1 = nI1; cI2 = nI2;
        cT0 = nT0; cT1 = nT1; cT2 = nT2;
    }

    // deterministic block reduction (reuse ring; only sync points in kernel)
    __syncthreads();
    ring[tid] = acc;
    __syncthreads();
    #pragma unroll
    for (int s = NT / 2; s > 0; s >>= 1) {
        if (tid < s) ring[tid] += ring[tid + s];
        __syncthreads();
    }
    if (tid == 0) g_part[b * YT + bx] = ring[0];
}

__global__ void fin_kernel(float* __restrict__ out) {
    __shared__ float s[512];
    int t = threadIdx.x;
    s[t] = (t < NPART) ? g_part[t] : 0.f;
    __syncthreads();
    #pragma unroll
    for (int k = 256; k > 0; k >>= 1) {
        if (t < k) s[t] += s[t + k];
        __syncthreads();
    }
    if (t == 0) out[0] = -s[0] * (1.0f / 8388608.0f);
}

extern "C" void kernel_launch(void* const* d_in, const int* in_sizes, int n_in,
                              void* d_out, int out_size) {
    const float* inp = (const float*)d_in[0];
    const float* tgt = (const float*)d_in[1];
    size_t smem = (size_t)(9 * 5 * 512) * sizeof(float);   // 92160 B
    cudaFuncSetAttribute(cc_kernel, cudaFuncAttributeMaxDynamicSharedMemorySize, (int)smem);
    dim3 grid(YT, NB);   // (9, 32) = 288 CTAs
    cc_kernel<<<grid, NT, smem>>>(inp, tgt);
    fin_kernel<<<1, 512>>>((float*)d_out);
}

// round 8
// speedup vs baseline: 1.5890x; 1.5890x over previous
#include <cuda_runtime.h>

// crossCorrelation3D: local 9x9 windowed cross-correlation loss.
// input (32,1,512,512) fp32, target (32,1,512,512) fp32 -> scalar.
//
// Vertical-first separable box sums:
//   - 5 vertical running sums (I,T,II,TT,IT) live in REGISTERS (f32x2 packed).
//   - row y-9 is subtracted by reloading it from global (L1-resident),
//     guarded so only rows that were actually accumulated are subtracted.
//   - horizontal 9-sum via a small double-buffered shared exchange (21 KB),
//     one __syncthreads per output row.
//   - packed f32x2 (FFMA2) arithmetic for all element-wise math.
// Grid = 18 ytiles x 32 batches = 576 CTAs, 128 thr x 4 cols, occ 4.

#define IMG_W 512
#define IMG_H 512
#define NB    32
#define HT    29
#define YT    18            // 17*29=493, last tile 19 rows
#define NT    128
#define CSTRIDE 520         // 4 pad + 512 + 4 pad
#define BUFF  (5*CSTRIDE)   // one exchange buffer (5 channels)
#define NPART (YT*NB)       // 576

__device__ float g_part[NPART];

// ---- packed f32x2 helpers ----
struct F2 { unsigned long long v; };

__device__ __forceinline__ F2 f2pk(float lo, float hi) {
    F2 r; asm("mov.b64 %0,{%1,%2};" : "=l"(r.v) : "f"(lo), "f"(hi)); return r;
}
__device__ __forceinline__ void f2up(F2 a, float& lo, float& hi) {
    asm("mov.b64 {%0,%1},%2;" : "=f"(lo), "=f"(hi) : "l"(a.v));
}
__device__ __forceinline__ F2 add2(F2 a, F2 b) {
    F2 r; asm("add.rn.f32x2 %0,%1,%2;" : "=l"(r.v) : "l"(a.v), "l"(b.v)); return r;
}
__device__ __forceinline__ F2 mul2(F2 a, F2 b) {
    F2 r; asm("mul.rn.f32x2 %0,%1,%2;" : "=l"(r.v) : "l"(a.v), "l"(b.v)); return r;
}
__device__ __forceinline__ F2 fma2(F2 a, F2 b, F2 c) {
    F2 r; asm("fma.rn.f32x2 %0,%1,%2,%3;" : "=l"(r.v) : "l"(a.v), "l"(b.v), "l"(c.v)); return r;
}
// a - b  (exact: fma(b,-1,a))
__device__ __forceinline__ F2 sub2(F2 a, F2 b, F2 neg1) { return fma2(b, neg1, a); }

__device__ __forceinline__ F2 f2z() { F2 r; r.v = 0ull; return r; }

// Load one row pair (I raw, T normalized to [0,1]).
// Valid iff ymin <= yi < IMG_H; otherwise zeros. For "old" (departing) rows
// ymin = y0-4 ensures we only subtract rows that were actually accumulated.
__device__ __forceinline__ void loadrow(const float* __restrict__ I,
                                        const float* __restrict__ T,
                                        int yi, int ymin, int tid, F2 H,
                                        F2& i0, F2& i1, F2& t0, F2& t1) {
    if (yi >= ymin && (unsigned)yi < (unsigned)IMG_H) {
        float4 a = __ldg((const float4*)(I + (size_t)yi * IMG_W) + tid);
        float4 b = __ldg((const float4*)(T + (size_t)yi * IMG_W) + tid);
        i0 = f2pk(a.x, a.y); i1 = f2pk(a.z, a.w);
        t0 = fma2(f2pk(b.x, b.y), H, H);   // (t+1)*0.5
        t1 = fma2(f2pk(b.z, b.w), H, H);
    } else {
        i0 = f2z(); i1 = f2z(); t0 = f2z(); t1 = f2z();
    }
}

// horizontal 9-sum over 12-col window (L0,L1 | O0,O1 | R0,R1) -> 4 outputs as 2 pairs
__device__ __forceinline__ void hsum9p(F2 L0, F2 L1, F2 O0, F2 O1, F2 R0, F2 R1,
                                       F2& hA, F2& hB) {
    F2 Q = add2(add2(L0, L1), add2(O0, O1));  // (w0+w2+w4+w6, w1+w3+w5+w7)
    float qlo, qhi, w0, w1, w2, wx, w8, w9, w10, w11;
    f2up(Q, qlo, qhi);
    f2up(L0, w0, w1);
    f2up(L1, w2, wx);
    f2up(R0, w8, w9);
    f2up(R1, w10, w11);
    float h0 = qlo + qhi + w8;
    float h1 = h0 - w0 + w9;
    float h2 = h1 - w1 + w10;
    float h3 = h2 - w2 + w11;
    hA = f2pk(h0, h1);
    hB = f2pk(h2, h3);
}

// packed cc for 2 outputs
__device__ __forceinline__ float cc2(F2 hI, F2 hT, F2 hII, F2 hTT, F2 hIT,
                                     F2 ninv, F2 eps2) {
    F2 cross = fma2(mul2(hI, hT), ninv, hIT);
    F2 tvar  = fma2(mul2(hT, hT), ninv, hTT);
    F2 ivar  = fma2(mul2(hI, hI), ninv, hII);
    F2 den   = fma2(tvar, ivar, eps2);
    F2 num   = mul2(cross, cross);
    float nlo, nhi, dlo, dhi;
    f2up(num, nlo, nhi);
    f2up(den, dlo, dhi);
    return __fdividef(nlo, dlo) + __fdividef(nhi, dhi);
}

__global__ __launch_bounds__(NT, 4)
void cc_kernel(const float* __restrict__ inp, const float* __restrict__ tgt) {
    extern __shared__ float sm[];   // 2 * BUFF floats (double-buffered exchange)

    const int tid = threadIdx.x;
    const int bx  = blockIdx.x;     // ytile
    const int b   = blockIdx.y;     // batch
    const int y0  = bx * HT;
    const int ymin = y0 - 4;        // first accumulated row index
    const int rows_out = min(HT, IMG_H - y0);
    const int iters = rows_out + 8;

    const float* Ib = inp + (size_t)b * IMG_H * IMG_W;
    const float* Tb = tgt + (size_t)b * IMG_H * IMG_W;

    // zero the left/right pads of both buffers (5 channels each)
    for (int i = tid; i < 2 * 5 * 8; i += NT) {
        int bf = i / 40, r = i % 40;
        int ch = r / 8, s = r % 8;
        int idx = (s < 4) ? s : (512 + s);  // 0..3 or 516..519
        sm[bf * BUFF + ch * CSTRIDE + idx] = 0.f;
    }
    __syncthreads();

    const F2 H    = f2pk(0.5f, 0.5f);
    const F2 NEG1 = f2pk(-1.f, -1.f);
    const F2 NINV = f2pk(-1.f / 81.f, -1.f / 81.f);
    const F2 EPS2 = f2pk(1e-5f, 1e-5f);

    F2 vI0 = f2z(), vI1 = f2z(), vT0 = f2z(), vT1 = f2z();
    F2 vII0 = f2z(), vII1 = f2z(), vTT0 = f2z(), vTT1 = f2z();
    F2 vIT0 = f2z(), vIT1 = f2z();
    float acc = 0.f;

    for (int it = 0; it < iters; ++it) {
        const int yn = y0 - 4 + it;     // new row entering the window
        const int yo = yn - 9;          // old row leaving

        F2 nI0, nI1, nT0, nT1, oI0, oI1, oT0, oT1;
        loadrow(Ib, Tb, yn, -(1 << 30), tid, H, nI0, nI1, nT0, nT1);
        // old row: subtract only if it was accumulated (yo >= ymin); rows in
        // [ymin, 0) were accumulated as zeros, handled by the 0<=yo<H check.
        loadrow(Ib, Tb, yo, ymin, tid, H, oI0, oI1, oT0, oT1);

        // vertical running sums: v += new - old (products recomputed)
        vI0 = add2(vI0, sub2(nI0, oI0, NEG1));
        vI1 = add2(vI1, sub2(nI1, oI1, NEG1));
        vT0 = add2(vT0, sub2(nT0, oT0, NEG1));
        vT1 = add2(vT1, sub2(nT1, oT1, NEG1));
        vII0 = add2(vII0, sub2(mul2(nI0, nI0), mul2(oI0, oI0), NEG1));
        vII1 = add2(vII1, sub2(mul2(nI1, nI1), mul2(oI1, oI1), NEG1));
        vTT0 = add2(vTT0, sub2(mul2(nT0, nT0), mul2(oT0, oT0), NEG1));
        vTT1 = add2(vTT1, sub2(mul2(nT1, nT1), mul2(oT1, oT1), NEG1));
        vIT0 = add2(vIT0, sub2(mul2(nI0, nT0), mul2(oI0, oT0), NEG1));
        vIT1 = add2(vIT1, sub2(mul2(nI1, nT1), mul2(oI1, oT1), NEG1));

        if (it >= 8) {
            float* buf = sm + (it & 1) * BUFF;
            // publish own vertical sums (one 16B store per channel)
            {
                ulonglong2 u;
                u.x = vI0.v;  u.y = vI1.v;
                *(ulonglong2*)&buf[0 * CSTRIDE + 4 + 4 * tid] = u;
                u.x = vT0.v;  u.y = vT1.v;
                *(ulonglong2*)&buf[1 * CSTRIDE + 4 + 4 * tid] = u;
                u.x = vII0.v; u.y = vII1.v;
                *(ulonglong2*)&buf[2 * CSTRIDE + 4 + 4 * tid] = u;
                u.x = vTT0.v; u.y = vTT1.v;
                *(ulonglong2*)&buf[3 * CSTRIDE + 4 + 4 * tid] = u;
                u.x = vIT0.v; u.y = vIT1.v;
                *(ulonglong2*)&buf[4 * CSTRIDE + 4 + 4 * tid] = u;
            }
            __syncthreads();

            // halo reads + horizontal sums
            F2 hIA, hIB, hTA, hTB, hIIA, hIIB, hTTA, hTTB, hITA, hITB;
            {
                ulonglong2 L, R; F2 l0, l1, r0, r1;
                L = *(ulonglong2*)&buf[0 * CSTRIDE + 4 * tid];
                R = *(ulonglong2*)&buf[0 * CSTRIDE + 8 + 4 * tid];
                l0.v = L.x; l1.v = L.y; r0.v = R.x; r1.v = R.y;
                hsum9p(l0, l1, vI0, vI1, r0, r1, hIA, hIB);
                L = *(ulonglong2*)&buf[1 * CSTRIDE + 4 * tid];
                R = *(ulonglong2*)&buf[1 * CSTRIDE + 8 + 4 * tid];
                l0.v = L.x; l1.v = L.y; r0.v = R.x; r1.v = R.y;
                hsum9p(l0, l1, vT0, vT1, r0, r1, hTA, hTB);
                L = *(ulonglong2*)&buf[2 * CSTRIDE + 4 * tid];
                R = *(ulonglong2*)&buf[2 * CSTRIDE + 8 + 4 * tid];
                l0.v = L.x; l1.v = L.y; r0.v = R.x; r1.v = R.y;
                hsum9p(l0, l1, vII0, vII1, r0, r1, hIIA, hIIB);
                L = *(ulonglong2*)&buf[3 * CSTRIDE + 4 * tid];
                R = *(ulonglong2*)&buf[3 * CSTRIDE + 8 + 4 * tid];
                l0.v = L.x; l1.v = L.y; r0.v = R.x; r1.v = R.y;
                hsum9p(l0, l1, vTT0, vTT1, r0, r1, hTTA, hTTB);
                L = *(ulonglong2*)&buf[4 * CSTRIDE + 4 * tid];
                R = *(ulonglong2*)&buf[4 * CSTRIDE + 8 + 4 * tid];
                l0.v = L.x; l1.v = L.y; r0.v = R.x; r1.v = R.y;
                hsum9p(l0, l1, vIT0, vIT1, r0, r1, hITA, hITB);
            }

            acc += cc2(hIA, hTA, hIIA, hTTA, hITA, NINV, EPS2);
            acc += cc2(hIB, hTB, hIIB, hTTB, hITB, NINV, EPS2);
        }
    }

    // deterministic block reduction (reuse exchange buffer)
    __syncthreads();
    sm[tid] = acc;
    __syncthreads();
    #pragma unroll
    for (int s = NT / 2; s > 0; s >>= 1) {
        if (tid < s) sm[tid] += sm[tid + s];
        __syncthreads();
    }
    if (tid == 0) g_part[b * YT + bx] = sm[0];
}

__global__ void fin_kernel(float* __restrict__ out) {
    __shared__ float s[512];
    int t = threadIdx.x;
    float v = (t < NPART) ? g_part[t] : 0.f;
    if (t + 512 < NPART) v += g_part[t + 512];
    s[t] = v;
    __syncthreads();
    #pragma unroll
    for (int k = 256; k > 0; k >>= 1) {
        if (t < k) s[t] += s[t + k];
        __syncthreads();
    }
    if (t == 0) out[0] = -s[0] * (1.0f / 8388608.0f);
}

extern "C" void kernel_launch(void* const* d_in, const int* in_sizes, int n_in,
                              void* d_out, int out_size) {
    const float* inp = (const float*)d_in[0];
    const float* tgt = (const float*)d_in[1];
    size_t smem = (size_t)(2 * BUFF) * sizeof(float);   // 20.8 KB
    cudaFuncSetAttribute(cc_kernel, cudaFuncAttributeMaxDynamicSharedMemorySize, (int)smem);
    dim3 grid(YT, NB);   // (18, 32) = 576 CTAs
    cc_kernel<<<grid, NT, smem>>>(inp, tgt);
    fin_kernel<<<1, 512>>>((float*)d_out);
}